// round 11
// baseline (speedup 1.0000x reference)
#include <cuda_runtime.h>
#include <math.h>
#include <stdint.h>

// Problem shape (fixed)
#define B_ 2
#define S_ 2048
#define E_ 1024
#define H_ 16
#define D_ 64
#define M_ROWS (B_ * S_)   // 4096
#define N_QKV (3 * E_)     // 3072

// Scratch. q/k tf32-pre-rounded, d-dim pair-permuted (perm8).
// v tf32-pre-rounded, TRANSPOSED [b,h,d,s] with s pair-permuted in 8-blocks.
__device__ float g_q[B_ * H_ * S_ * D_];
__device__ float g_k[B_ * H_ * S_ * D_];
__device__ float g_v[B_ * H_ * D_ * S_];   // transposed!
__device__ float g_ao[B_ * S_ * E_];
__device__ float g_wqkv_t[(size_t)N_QKV * E_];  // Wqkv^T [N][K], tf32-rounded
__device__ float g_wout_t[(size_t)E_ * E_];     // Wout^T [N][K], tf32-rounded

// pair permute within 8-block: logical x -> 2*(x%4) + x/4 (so x, x+4 adjacent)
__device__ __forceinline__ int perm8(int x) {
    return (x & ~7) | (((x & 3) << 1) | ((x & 7) >> 2));
}

__device__ __forceinline__ uint32_t cvt_tf32(float f) {
    uint32_t u;
    asm("cvt.rn.tf32.f32 %0, %1;" : "=r"(u) : "f"(f));
    return u;
}
__device__ __forceinline__ float rnd_tf32(float f) {
    return __uint_as_float(cvt_tf32(f));
}

__device__ __forceinline__ void mma_tf32(float* c, const uint32_t* a,
                                         const uint32_t* b) {
    asm volatile(
        "mma.sync.aligned.m16n8k8.row.col.f32.tf32.tf32.f32 "
        "{%0,%1,%2,%3}, {%4,%5,%6,%7}, {%8,%9}, {%0,%1,%2,%3};"
        : "+f"(c[0]), "+f"(c[1]), "+f"(c[2]), "+f"(c[3])
        : "r"(a[0]), "r"(a[1]), "r"(a[2]), "r"(a[3]), "r"(b[0]), "r"(b[1]));
}

__device__ __forceinline__ uint32_t smem_u32(const void* p) {
    uint32_t a;
    asm("{ .reg .u64 t; cvta.to.shared.u64 t, %1; cvt.u32.u64 %0, t; }"
        : "=r"(a) : "l"(p));
    return a;
}

__device__ __forceinline__ void cp16(uint32_t dst, const void* src) {
    asm volatile("cp.async.cg.shared.global [%0], [%1], 16;"
                 :: "r"(dst), "l"(src));
}
#define CP_COMMIT() asm volatile("cp.async.commit_group;" ::: "memory")
#define CP_WAIT0()  asm volatile("cp.async.wait_group 0;" ::: "memory")

// ---------------------------------------------------------------------------
// Weight transpose + tf32 rounding:  Wt[n][k] = rn_tf32(W[k][n])
// ---------------------------------------------------------------------------
__device__ __forceinline__ void transpose_body(const float* __restrict__ W,
                                               float* __restrict__ Wt,
                                               int K, int N) {
    __shared__ float tile[32][33];
    int n0 = blockIdx.x * 32, k0 = blockIdx.y * 32;
    int tx = threadIdx.x, ty = threadIdx.y;
    for (int i = ty; i < 32; i += 8)
        tile[i][tx] = W[(size_t)(k0 + i) * N + n0 + tx];
    __syncthreads();
    for (int i = ty; i < 32; i += 8)
        Wt[(size_t)(n0 + i) * K + k0 + tx] = rnd_tf32(tile[tx][i]);
}

__global__ void transpose_qkv_kernel(const float* __restrict__ W) {
    transpose_body(W, g_wqkv_t, E_, N_QKV);
}
__global__ void transpose_out_kernel(const float* __restrict__ W) {
    transpose_body(W, g_wout_t, E_, E_);
}

// ---------------------------------------------------------------------------
// tf32 mma.sync projection GEMM core (R5 structure — measured fastest).
// ---------------------------------------------------------------------------
#define BK 32
#define TSTRIDE 36
#define TILE_WORDS (128 * TSTRIDE)
#define GEMM_DYN_SMEM (2 * 2 * TILE_WORDS * 4)   // 73728 B

struct GemmFrag {
    float acc[4][4][4];   // [mfrag][nfrag][reg]
};

__device__ __forceinline__ void ldg_tile(const float* __restrict__ G,
                                         int rowbase, int kb, int tid,
                                         float4* r) {
    #pragma unroll
    for (int i = 0; i < 4; i++) {
        int idx = tid + i * 256;
        int row = idx >> 3, c4 = idx & 7;
        r[i] = *(const float4*)(G + (size_t)(rowbase + row) * E_ + kb * BK + c4 * 4);
    }
}

__device__ __forceinline__ void sts_tile(float* Sm, int tid, const float4* r) {
    #pragma unroll
    for (int i = 0; i < 4; i++) {
        int idx = tid + i * 256;
        int row = idx >> 3, c4 = idx & 7;
        uint32_t* p = (uint32_t*)(Sm + row * TSTRIDE + c4 * 4);
        p[0] = cvt_tf32(r[i].x);
        p[1] = cvt_tf32(r[i].y);
        p[2] = cvt_tf32(r[i].z);
        p[3] = cvt_tf32(r[i].w);
    }
}

__device__ __forceinline__ void gemm_compute(const float* As, const float* Bs,
                                             int warpM, int warpN, int lane,
                                             GemmFrag& F) {
    int g = lane >> 2, t4 = lane & 3;
    #pragma unroll
    for (int c = 0; c < 4; c++) {
        int k0 = c * 8;
        uint32_t a[4][4], b[4][2];
        #pragma unroll
        for (int mf = 0; mf < 4; mf++) {
            const float* ap = As + (warpM * 64 + mf * 16 + g) * TSTRIDE + k0 + t4;
            a[mf][0] = __float_as_uint(ap[0]);
            a[mf][1] = __float_as_uint(ap[8 * TSTRIDE]);
            a[mf][2] = __float_as_uint(ap[4]);
            a[mf][3] = __float_as_uint(ap[8 * TSTRIDE + 4]);
        }
        #pragma unroll
        for (int nf = 0; nf < 4; nf++) {
            const float* bp = Bs + (warpN * 32 + nf * 8 + g) * TSTRIDE + k0 + t4;
            b[nf][0] = __float_as_uint(bp[0]);
            b[nf][1] = __float_as_uint(bp[4]);
        }
        #pragma unroll
        for (int mf = 0; mf < 4; mf++)
            #pragma unroll
            for (int nf = 0; nf < 4; nf++)
                mma_tf32(F.acc[mf][nf], a[mf], b[nf]);
    }
}

__device__ __forceinline__ void gemm_mainloop(const float* __restrict__ A,
                                              const float* __restrict__ Bt,
                                              int row0, int col0,
                                              float* dynsm, int tid,
                                              int warpM, int warpN, int lane,
                                              GemmFrag& F) {
    float* As[2] = { dynsm,              dynsm + 2 * TILE_WORDS };
    float* Bs[2] = { dynsm + TILE_WORDS, dynsm + 3 * TILE_WORDS };

    float4 ra[4], rb[4];
    ldg_tile(A,  row0, 0, tid, ra);
    ldg_tile(Bt, col0, 0, tid, rb);
    sts_tile(As[0], tid, ra);
    sts_tile(Bs[0], tid, rb);
    __syncthreads();

    const int NBK = E_ / BK;
    for (int kb = 0; kb < NBK; kb++) {
        int cur = kb & 1;
        if (kb + 1 < NBK) {
            ldg_tile(A,  row0, kb + 1, tid, ra);
            ldg_tile(Bt, col0, kb + 1, tid, rb);
        }
        gemm_compute(As[cur], Bs[cur], warpM, warpN, lane, F);
        if (kb + 1 < NBK) {
            sts_tile(As[cur ^ 1], tid, ra);
            sts_tile(Bs[cur ^ 1], tid, rb);
        }
        __syncthreads();
    }
}

// --- QKV GEMM: epilogue scatters tf32-rounded values into permuted layouts ---
__global__ __launch_bounds__(256) void qkv_mma_kernel(
    const float* __restrict__ X, const float* __restrict__ bias)
{
    extern __shared__ float dynsm[];
    int tid = threadIdx.x, wid = tid >> 5, lane = tid & 31;
    int warpM = wid & 1, warpN = wid >> 1;
    int row0 = blockIdx.y * 128, col0 = blockIdx.x * 128;

    GemmFrag F;
    #pragma unroll
    for (int i = 0; i < 4; i++)
        #pragma unroll
        for (int j = 0; j < 4; j++)
            #pragma unroll
            for (int k = 0; k < 4; k++) F.acc[i][j][k] = 0.f;

    gemm_mainloop(X, g_wqkv_t, row0, col0, dynsm, tid, warpM, warpN, lane, F);

    int g = lane >> 2, t4 = lane & 3;
    int t = col0 >> 10;   // 0=q 1=k 2=v (whole block in one third)

    #pragma unroll
    for (int mf = 0; mf < 4; mf++) {
        #pragma unroll
        for (int nf = 0; nf < 4; nf++) {
            int col = col0 + warpN * 32 + nf * 8 + 2 * t4;
            int h = (col & 1023) >> 6;
            int d = col & 63;
            float bx = bias[col], by = bias[col + 1];
            #pragma unroll
            for (int rr = 0; rr < 2; rr++) {
                int row = row0 + warpM * 64 + mf * 16 + g + rr * 8;
                int bb = row >> 11, s = row & (S_ - 1);
                float vx = rnd_tf32(F.acc[mf][nf][rr * 2 + 0] + bx);
                float vy = rnd_tf32(F.acc[mf][nf][rr * 2 + 1] + by);
                if (t == 2) {
                    // V transposed [b,h,d,s], s pair-permuted in 8-blocks
                    int sp = perm8(s);
                    size_t base = ((size_t)(bb * H_ + h)) * D_;
                    g_v[(base + d)     * S_ + sp] = vx;
                    g_v[(base + d + 1) * S_ + sp] = vy;
                } else {
                    // Q/K: [b,h,s,d], d pair-permuted in 8-blocks
                    float* dst = (t == 0) ? g_q : g_k;
                    float* dp = dst + ((size_t)((bb * H_ + h) * S_ + s)) * D_;
                    dp[perm8(d)]     = vx;
                    dp[perm8(d + 1)] = vy;
                }
            }
        }
    }
}

// --- Output GEMM: plain epilogue to d_out ---
__global__ __launch_bounds__(256) void out_mma_kernel(
    const float* __restrict__ bias, float* __restrict__ out)
{
    extern __shared__ float dynsm[];
    int tid = threadIdx.x, wid = tid >> 5, lane = tid & 31;
    int warpM = wid & 1, warpN = wid >> 1;
    int row0 = blockIdx.y * 128, col0 = blockIdx.x * 128;

    GemmFrag F;
    #pragma unroll
    for (int i = 0; i < 4; i++)
        #pragma unroll
        for (int j = 0; j < 4; j++)
            #pragma unroll
            for (int k = 0; k < 4; k++) F.acc[i][j][k] = 0.f;

    gemm_mainloop(g_ao, g_wout_t, row0, col0, dynsm, tid, warpM, warpN, lane, F);

    int g = lane >> 2, t4 = lane & 3;
    #pragma unroll
    for (int mf = 0; mf < 4; mf++) {
        #pragma unroll
        for (int nf = 0; nf < 4; nf++) {
            int col = col0 + warpN * 32 + nf * 8 + 2 * t4;
            float bx = bias[col], by = bias[col + 1];
            #pragma unroll
            for (int rr = 0; rr < 2; rr++) {
                int row = row0 + warpM * 64 + mf * 16 + g + rr * 8;
                float2 v;
                v.x = F.acc[mf][nf][rr * 2 + 0] + bx;
                v.y = F.acc[mf][nf][rr * 2 + 1] + by;
                *(float2*)(out + (size_t)row * E_ + col) = v;
            }
        }
    }
}

// ---------------------------------------------------------------------------
// Flash attention, tf32 mma.sync, no-max softmax.
// Grid (S/128, B*H), 128 threads = 4 warps; warp owns 32 q-rows (two m16
// halves sharing every K/V b-fragment).  Q fragments in registers.
// Pair-permuted operand layouts -> all B fragments are single LDS.64.
// SMEM (floats, stride 72): Kt[64 keys][64 d], Vt[64 d][64 keys], P, mk.
// ---------------------------------------------------------------------------
#define AKT 64
#define ASTR 72
#define AKT_OFF 0
#define AVT_OFF (64 * ASTR)
#define AP_OFF  (AVT_OFF + 64 * ASTR)
#define AMK_OFF (AP_OFF + 128 * ASTR)
#define ATTN_DYN_SMEM ((AMK_OFF + 64) * 4)   // 73984 B

__global__ __launch_bounds__(128, 2) void attn_mma_kernel(const int* __restrict__ mask)
{
    extern __shared__ float sm[];
    float* Kt = sm + AKT_OFF;
    float* Vt = sm + AVT_OFF;
    float* P  = sm + AP_OFF;
    float* mk = sm + AMK_OFF;
    uint32_t kt_u = smem_u32(Kt), vt_u = smem_u32(Vt);

    int tid = threadIdx.x, w = tid >> 5, lane = tid & 31;
    int g = lane >> 2, t4 = lane & 3;
    int bh = blockIdx.y;
    int b = bh >> 4, h = bh & 15;
    int q0 = blockIdx.x * 128;
    int wrow = w * 32;

    const float* Qb = g_q + (size_t)bh * S_ * D_;
    const float* Kb = g_k + (size_t)bh * S_ * D_;
    const float* Vb = g_v + (size_t)bh * D_ * S_;   // transposed [d][s]

    // Prefetch K/V tile 0.  K: rows=keys, 64x64.  V: rows=d, cols=keys.
    #pragma unroll
    for (int i = 0; i < 8; i++) {
        int idx = tid + i * 128;
        int row = idx >> 4, c4 = (idx & 15) * 4;
        cp16(kt_u + (uint32_t)(row * ASTR + c4) * 4,
             Kb + (size_t)row * D_ + c4);
        cp16(vt_u + (uint32_t)(row * ASTR + c4) * 4,
             Vb + (size_t)row * S_ + c4);
    }
    CP_COMMIT();
    if (tid < AKT)
        mk[tid] = (mask[b * S_ + tid] == 0) ? -INFINITY : 0.f;

    // Q fragments in registers (gmem is d-pair-permuted: float2 at 2*t4
    // gives logical d = t4 (lo) and t4+4 (hi)).
    uint32_t qa0[8][4], qa1[8][4];
    {
        const float* qr0 = Qb + (size_t)(q0 + wrow + g) * D_;
        #pragma unroll
        for (int dc = 0; dc < 8; dc++) {
            int off = dc * 8 + 2 * t4;
            float2 v0 = *(const float2*)(qr0 + off);
            float2 v1 = *(const float2*)(qr0 + 8 * D_ + off);
            float2 v2 = *(const float2*)(qr0 + 16 * D_ + off);
            float2 v3 = *(const float2*)(qr0 + 24 * D_ + off);
            qa0[dc][0] = __float_as_uint(v0.x);
            qa0[dc][1] = __float_as_uint(v1.x);
            qa0[dc][2] = __float_as_uint(v0.y);
            qa0[dc][3] = __float_as_uint(v1.y);
            qa1[dc][0] = __float_as_uint(v2.x);
            qa1[dc][1] = __float_as_uint(v3.x);
            qa1[dc][2] = __float_as_uint(v2.y);
            qa1[dc][3] = __float_as_uint(v3.y);
        }
    }

    float ov0[8][4], ov1[8][4];
    #pragma unroll
    for (int i = 0; i < 8; i++)
        #pragma unroll
        for (int j = 0; j < 4; j++) { ov0[i][j] = 0.f; ov1[i][j] = 0.f; }
    float l00 = 0.f, l01 = 0.f, l10 = 0.f, l11 = 0.f;

    for (int kt = 0; kt < S_; kt += AKT) {
        CP_WAIT0();
        __syncthreads();

        // QK^T, both 16-row halves; B fragment = single LDS.64
        float s0[8][4], s1[8][4];
        #pragma unroll
        for (int i = 0; i < 8; i++)
            #pragma unroll
            for (int j = 0; j < 4; j++) { s0[i][j] = 0.f; s1[i][j] = 0.f; }
        #pragma unroll
        for (int dc = 0; dc < 8; dc++) {
            #pragma unroll
            for (int nf = 0; nf < 8; nf++) {
                float2 bv = *(const float2*)(Kt + (nf * 8 + g) * ASTR
                                             + dc * 8 + 2 * t4);
                uint32_t bb[2] = { __float_as_uint(bv.x),
                                   __float_as_uint(bv.y) };
                mma_tf32(s0[nf], qa0[dc], bb);
                mma_tf32(s1[nf], qa1[dc], bb);
            }
        }

        // exp (no max subtraction; mask via -inf), accumulate l, store tf32 P
        #pragma unroll
        for (int nf = 0; nf < 8; nf++) {
            float am0 = mk[nf * 8 + 2 * t4], am1 = mk[nf * 8 + 2 * t4 + 1];
            float p00 = __expf(fmaf(s0[nf][0], 0.125f, am0));
            float p01 = __expf(fmaf(s0[nf][1], 0.125f, am1));
            float p02 = __expf(fmaf(s0[nf][2], 0.125f, am0));
            float p03 = __expf(fmaf(s0[nf][3], 0.125f, am1));
            float p10 = __expf(fmaf(s1[nf][0], 0.125f, am0));
            float p11 = __expf(fmaf(s1[nf][1], 0.125f, am1));
            float p12 = __expf(fmaf(s1[nf][2], 0.125f, am0));
            float p13 = __expf(fmaf(s1[nf][3], 0.125f, am1));
            l00 += p00 + p01; l01 += p02 + p03;
            l10 += p10 + p11; l11 += p12 + p13;
            uint32_t* d;
            d = (uint32_t*)(P + (wrow + g) * ASTR + nf * 8 + 2 * t4);
            d[0] = cvt_tf32(p00); d[1] = cvt_tf32(p01);
            d = (uint32_t*)(P + (wrow + 8 + g) * ASTR + nf * 8 + 2 * t4);
            d[0] = cvt_tf32(p02); d[1] = cvt_tf32(p03);
            d = (uint32_t*)(P + (wrow + 16 + g) * ASTR + nf * 8 + 2 * t4);
            d[0] = cvt_tf32(p10); d[1] = cvt_tf32(p11);
            d = (uint32_t*)(P + (wrow + 24 + g) * ASTR + nf * 8 + 2 * t4);
            d[0] = cvt_tf32(p12); d[1] = cvt_tf32(p13);
        }
        __syncwarp();   // P round-trip is warp-local

        // PV, both halves; V is d-major with key-pair-permute:
        // LDS.64 at (d row, key 2*t4) = logical keys (t4, t4+4).
        #pragma unroll
        for (int kc = 0; kc < 8; kc++) {
            const float* pa0 = P + (wrow + g) * ASTR + kc * 8 + t4;
            const float* pa1 = P + (wrow + 16 + g) * ASTR + kc * 8 + t4;
            uint32_t a0[4] = { __float_as_uint(pa0[0]),
                               __float_as_uint(pa0[8 * ASTR]),
                               __float_as_uint(pa0[4]),
                               __float_as_uint(pa0[8 * ASTR + 4]) };
            uint32_t a1[4] = { __float_as_uint(pa1[0]),
                               __float_as_uint(pa1[8 * ASTR]),
                               __float_as_uint(pa1[4]),
                               __float_as_uint(pa1[8 * ASTR + 4]) };
            #pragma unroll
            for (int nf = 0; nf < 8; nf++) {
                float2 vv = *(const float2*)(Vt + (nf * 8 + g) * ASTR
                                             + kc * 8 + 2 * t4);
                uint32_t bb[2] = { __float_as_uint(vv.x),
                                   __float_as_uint(vv.y) };
                mma_tf32(ov0[nf], a0, bb);
                mma_tf32(ov1[nf], a1, bb);
            }
        }

        // Stage next tile (after all reads of current Kt/Vt are done).
        if (kt + AKT < S_) {
            __syncthreads();
            #pragma unroll
            for (int i = 0; i < 8; i++) {
                int idx = tid + i * 128;
                int row = idx >> 4, c4 = (idx & 15) * 4;
                cp16(kt_u + (uint32_t)(row * ASTR + c4) * 4,
                     Kb + (size_t)(kt + AKT + row) * D_ + c4);
                cp16(vt_u + (uint32_t)(row * ASTR + c4) * 4,
                     Vb + (size_t)row * S_ + kt + AKT + c4);
            }
            CP_COMMIT();
            if (tid < AKT)
                mk[tid] = (mask[b * S_ + kt + AKT + tid] == 0) ? -INFINITY : 0.f;
        }
    }

    // quad-reduce l, normalize, write g_ao [b, s, h*64+d]
    l00 += __shfl_xor_sync(0xffffffffu, l00, 1);
    l00 += __shfl_xor_sync(0xffffffffu, l00, 2);
    l01 += __shfl_xor_sync(0xffffffffu, l01, 1);
    l01 += __shfl_xor_sync(0xffffffffu, l01, 2);
    l10 += __shfl_xor_sync(0xffffffffu, l10, 1);
    l10 += __shfl_xor_sync(0xffffffffu, l10, 2);
    l11 += __shfl_xor_sync(0xffffffffu, l11, 1);
    l11 += __shfl_xor_sync(0xffffffffu, l11, 2);
    float i00 = 1.f / l00, i01 = 1.f / l01, i10 = 1.f / l10, i11 = 1.f / l11;

    int r0 = q0 + wrow + g;
    float* oA = g_ao + ((size_t)(b * S_ + r0))      * E_ + h * D_;
    float* oB = g_ao + ((size_t)(b * S_ + r0 + 8))  * E_ + h * D_;
    float* oC = g_ao + ((size_t)(b * S_ + r0 + 16)) * E_ + h * D_;
    float* oD = g_ao + ((size_t)(b * S_ + r0 + 24)) * E_ + h * D_;
    #pragma unroll
    for (int nf = 0; nf < 8; nf++) {
        int d = nf * 8 + 2 * t4;
        float2 vA = { ov0[nf][0] * i00, ov0[nf][1] * i00 };
        float2 vB = { ov0[nf][2] * i01, ov0[nf][3] * i01 };
        float2 vC = { ov1[nf][0] * i10, ov1[nf][1] * i10 };
        float2 vD = { ov1[nf][2] * i11, ov1[nf][3] * i11 };
        *(float2*)(oA + d) = vA;
        *(float2*)(oB + d) = vB;
        *(float2*)(oC + d) = vC;
        *(float2*)(oD + d) = vD;
    }
}

// ---------------------------------------------------------------------------
extern "C" void kernel_launch(void* const* d_in, const int* in_sizes, int n_in,
                              void* d_out, int out_size)
{
    const float* x    = (const float*)d_in[0];
    const int*   mask = (const int*)  d_in[1];
    const float* Wqkv = (const float*)d_in[2];
    const float* bqkv = (const float*)d_in[3];
    const float* Wout = (const float*)d_in[4];
    const float* bout = (const float*)d_in[5];
    float* out = (float*)d_out;
    (void)in_sizes; (void)n_in; (void)out_size;

    static bool attr_done = false;
    if (!attr_done) {
        cudaFuncSetAttribute(qkv_mma_kernel,
                             cudaFuncAttributeMaxDynamicSharedMemorySize, GEMM_DYN_SMEM);
        cudaFuncSetAttribute(out_mma_kernel,
                             cudaFuncAttributeMaxDynamicSharedMemorySize, GEMM_DYN_SMEM);
        cudaFuncSetAttribute(attn_mma_kernel,
                             cudaFuncAttributeMaxDynamicSharedMemorySize, ATTN_DYN_SMEM);
        attr_done = true;
    }

    transpose_qkv_kernel<<<dim3(N_QKV / 32, E_ / 32), dim3(32, 8)>>>(Wqkv);
    transpose_out_kernel<<<dim3(E_ / 32, E_ / 32), dim3(32, 8)>>>(Wout);

    dim3 g1(N_QKV / 128, M_ROWS / 128);   // 24 x 32
    qkv_mma_kernel<<<g1, 256, GEMM_DYN_SMEM>>>(x, bqkv);

    dim3 g2(S_ / 128, B_ * H_);           // 16 x 32
    attn_mma_kernel<<<g2, 128, ATTN_DYN_SMEM>>>(mask);

    dim3 g3(E_ / 128, M_ROWS / 128);      // 8 x 32
    out_mma_kernel<<<g3, 256, GEMM_DYN_SMEM>>>(bout, out);
}

// round 15
// speedup vs baseline: 1.1087x; 1.1087x over previous
#include <cuda_runtime.h>
#include <math.h>
#include <stdint.h>

// Problem shape (fixed)
#define B_ 2
#define S_ 2048
#define E_ 1024
#define H_ 16
#define D_ 64
#define M_ROWS (B_ * S_)   // 4096
#define N_QKV (3 * E_)     // 3072

// Scratch (__device__ globals per allocation rules). q/k/v tf32-pre-rounded.
__device__ float g_q[B_ * H_ * S_ * D_];   // [b,h,s,d]
__device__ float g_k[B_ * H_ * S_ * D_];
__device__ float g_v[B_ * H_ * S_ * D_];
__device__ float g_ao[B_ * S_ * E_];       // [b,s,e]
__device__ float g_wqkv_t[(size_t)N_QKV * E_];  // Wqkv^T [N][K], tf32-rounded
__device__ float g_wout_t[(size_t)E_ * E_];     // Wout^T [N][K], tf32-rounded

__device__ __forceinline__ uint32_t cvt_tf32(float f) {
    uint32_t u;
    asm("cvt.rn.tf32.f32 %0, %1;" : "=r"(u) : "f"(f));
    return u;
}
__device__ __forceinline__ float rnd_tf32(float f) {
    return __uint_as_float(cvt_tf32(f));
}

__device__ __forceinline__ void mma_tf32(float* c, const uint32_t* a,
                                         const uint32_t* b) {
    asm volatile(
        "mma.sync.aligned.m16n8k8.row.col.f32.tf32.tf32.f32 "
        "{%0,%1,%2,%3}, {%4,%5,%6,%7}, {%8,%9}, {%0,%1,%2,%3};"
        : "+f"(c[0]), "+f"(c[1]), "+f"(c[2]), "+f"(c[3])
        : "r"(a[0]), "r"(a[1]), "r"(a[2]), "r"(a[3]), "r"(b[0]), "r"(b[1]));
}

__device__ __forceinline__ uint32_t smem_u32(const void* p) {
    uint32_t a;
    asm("{ .reg .u64 t; cvta.to.shared.u64 t, %1; cvt.u32.u64 %0, t; }"
        : "=r"(a) : "l"(p));
    return a;
}

__device__ __forceinline__ void cp16(uint32_t dst, const void* src) {
    asm volatile("cp.async.cg.shared.global [%0], [%1], 16;"
                 :: "r"(dst), "l"(src));
}
#define CP_COMMIT() asm volatile("cp.async.commit_group;" ::: "memory")
#define CP_WAIT0()  asm volatile("cp.async.wait_group 0;" ::: "memory")

// ---------------------------------------------------------------------------
// Weight transpose + tf32 rounding:  Wt[n][k] = rn_tf32(W[k][n])
// ---------------------------------------------------------------------------
__device__ __forceinline__ void transpose_body(const float* __restrict__ W,
                                               float* __restrict__ Wt,
                                               int K, int N) {
    __shared__ float tile[32][33];
    int n0 = blockIdx.x * 32, k0 = blockIdx.y * 32;
    int tx = threadIdx.x, ty = threadIdx.y;
    for (int i = ty; i < 32; i += 8)
        tile[i][tx] = W[(size_t)(k0 + i) * N + n0 + tx];
    __syncthreads();
    for (int i = ty; i < 32; i += 8)
        Wt[(size_t)(n0 + i) * K + k0 + tx] = rnd_tf32(tile[tx][i]);
}

__global__ void transpose_qkv_kernel(const float* __restrict__ W) {
    transpose_body(W, g_wqkv_t, E_, N_QKV);
}
__global__ void transpose_out_kernel(const float* __restrict__ W) {
    transpose_body(W, g_wout_t, E_, E_);
}

// ---------------------------------------------------------------------------
// tf32 mma.sync projection GEMM core (R5/R10 structure — measured fastest).
// ---------------------------------------------------------------------------
#define BK 32
#define TSTRIDE 36
#define TILE_WORDS (128 * TSTRIDE)
#define GEMM_DYN_SMEM (2 * 2 * TILE_WORDS * 4)   // 73728 B

struct GemmFrag {
    float acc[4][4][4];   // [mfrag][nfrag][reg]
};

__device__ __forceinline__ void ldg_tile(const float* __restrict__ G,
                                         int rowbase, int kb, int tid,
                                         float4* r) {
    #pragma unroll
    for (int i = 0; i < 4; i++) {
        int idx = tid + i * 256;
        int row = idx >> 3, c4 = idx & 7;
        r[i] = *(const float4*)(G + (size_t)(rowbase + row) * E_ + kb * BK + c4 * 4);
    }
}

__device__ __forceinline__ void sts_tile(float* Sm, int tid, const float4* r) {
    #pragma unroll
    for (int i = 0; i < 4; i++) {
        int idx = tid + i * 256;
        int row = idx >> 3, c4 = idx & 7;
        uint32_t* p = (uint32_t*)(Sm + row * TSTRIDE + c4 * 4);
        p[0] = cvt_tf32(r[i].x);
        p[1] = cvt_tf32(r[i].y);
        p[2] = cvt_tf32(r[i].z);
        p[3] = cvt_tf32(r[i].w);
    }
}

__device__ __forceinline__ void gemm_compute(const float* As, const float* Bs,
                                             int warpM, int warpN, int lane,
                                             GemmFrag& F) {
    int g = lane >> 2, t4 = lane & 3;
    #pragma unroll
    for (int c = 0; c < 4; c++) {
        int k0 = c * 8;
        uint32_t a[4][4], b[4][2];
        #pragma unroll
        for (int mf = 0; mf < 4; mf++) {
            const float* ap = As + (warpM * 64 + mf * 16 + g) * TSTRIDE + k0 + t4;
            a[mf][0] = __float_as_uint(ap[0]);
            a[mf][1] = __float_as_uint(ap[8 * TSTRIDE]);
            a[mf][2] = __float_as_uint(ap[4]);
            a[mf][3] = __float_as_uint(ap[8 * TSTRIDE + 4]);
        }
        #pragma unroll
        for (int nf = 0; nf < 4; nf++) {
            const float* bp = Bs + (warpN * 32 + nf * 8 + g) * TSTRIDE + k0 + t4;
            b[nf][0] = __float_as_uint(bp[0]);
            b[nf][1] = __float_as_uint(bp[4]);
        }
        #pragma unroll
        for (int mf = 0; mf < 4; mf++)
            #pragma unroll
            for (int nf = 0; nf < 4; nf++)
                mma_tf32(F.acc[mf][nf], a[mf], b[nf]);
    }
}

__device__ __forceinline__ void gemm_mainloop(const float* __restrict__ A,
                                              const float* __restrict__ Bt,
                                              int row0, int col0,
                                              float* dynsm, int tid,
                                              int warpM, int warpN, int lane,
                                              GemmFrag& F) {
    float* As[2] = { dynsm,              dynsm + 2 * TILE_WORDS };
    float* Bs[2] = { dynsm + TILE_WORDS, dynsm + 3 * TILE_WORDS };

    float4 ra[4], rb[4];
    ldg_tile(A,  row0, 0, tid, ra);
    ldg_tile(Bt, col0, 0, tid, rb);
    sts_tile(As[0], tid, ra);
    sts_tile(Bs[0], tid, rb);
    __syncthreads();

    const int NBK = E_ / BK;
    for (int kb = 0; kb < NBK; kb++) {
        int cur = kb & 1;
        if (kb + 1 < NBK) {
            ldg_tile(A,  row0, kb + 1, tid, ra);
            ldg_tile(Bt, col0, kb + 1, tid, rb);
        }
        gemm_compute(As[cur], Bs[cur], warpM, warpN, lane, F);
        if (kb + 1 < NBK) {
            sts_tile(As[cur ^ 1], tid, ra);
            sts_tile(Bs[cur ^ 1], tid, rb);
        }
        __syncthreads();
    }
}

// --- QKV GEMM: epilogue scatters tf32-rounded values into g_q/g_k/g_v ---
__global__ __launch_bounds__(256) void qkv_mma_kernel(
    const float* __restrict__ X, const float* __restrict__ bias)
{
    extern __shared__ float dynsm[];
    int tid = threadIdx.x, wid = tid >> 5, lane = tid & 31;
    int warpM = wid & 1, warpN = wid >> 1;
    int row0 = blockIdx.y * 128, col0 = blockIdx.x * 128;

    GemmFrag F;
    #pragma unroll
    for (int i = 0; i < 4; i++)
        #pragma unroll
        for (int j = 0; j < 4; j++)
            #pragma unroll
            for (int k = 0; k < 4; k++) F.acc[i][j][k] = 0.f;

    gemm_mainloop(X, g_wqkv_t, row0, col0, dynsm, tid, warpM, warpN, lane, F);

    int g = lane >> 2, t4 = lane & 3;
    int t = col0 >> 10;
    float* dst = (t == 0) ? g_q : (t == 1) ? g_k : g_v;

    #pragma unroll
    for (int mf = 0; mf < 4; mf++) {
        #pragma unroll
        for (int nf = 0; nf < 4; nf++) {
            int col = col0 + warpN * 32 + nf * 8 + 2 * t4;
            int h = (col & 1023) >> 6;
            int d = col & 63;
            float bx = bias[col], by = bias[col + 1];
            #pragma unroll
            for (int rr = 0; rr < 2; rr++) {
                int row = row0 + warpM * 64 + mf * 16 + g + rr * 8;
                int bb = row >> 11, s = row & (S_ - 1);
                float2 v;
                v.x = rnd_tf32(F.acc[mf][nf][rr * 2 + 0] + bx);  // pre-round
                v.y = rnd_tf32(F.acc[mf][nf][rr * 2 + 1] + by);
                *(float2*)(dst + ((size_t)((bb * H_ + h) * S_ + s)) * D_ + d) = v;
            }
        }
    }
}

// --- Output GEMM: plain epilogue to d_out ---
__global__ __launch_bounds__(256) void out_mma_kernel(
    const float* __restrict__ bias, float* __restrict__ out)
{
    extern __shared__ float dynsm[];
    int tid = threadIdx.x, wid = tid >> 5, lane = tid & 31;
    int warpM = wid & 1, warpN = wid >> 1;
    int row0 = blockIdx.y * 128, col0 = blockIdx.x * 128;

    GemmFrag F;
    #pragma unroll
    for (int i = 0; i < 4; i++)
        #pragma unroll
        for (int j = 0; j < 4; j++)
            #pragma unroll
            for (int k = 0; k < 4; k++) F.acc[i][j][k] = 0.f;

    gemm_mainloop(g_ao, g_wout_t, row0, col0, dynsm, tid, warpM, warpN, lane, F);

    int g = lane >> 2, t4 = lane & 3;
    #pragma unroll
    for (int mf = 0; mf < 4; mf++) {
        #pragma unroll
        for (int nf = 0; nf < 4; nf++) {
            int col = col0 + warpN * 32 + nf * 8 + 2 * t4;
            float bx = bias[col], by = bias[col + 1];
            #pragma unroll
            for (int rr = 0; rr < 2; rr++) {
                int row = row0 + warpM * 64 + mf * 16 + g + rr * 8;
                float2 v;
                v.x = F.acc[mf][nf][rr * 2 + 0] + bx;
                v.y = F.acc[mf][nf][rr * 2 + 1] + by;
                *(float2*)(out + (size_t)row * E_ + col) = v;
            }
        }
    }
}

// ---------------------------------------------------------------------------
// Flash attention, tf32 mma.sync, no-max softmax, REGISTER-RESIDENT P.
// Grid (S/128, B*H), 128 threads = 4 warps; warp owns 32 q-rows (two m16
// halves sharing every K/V b-fragment).  Q fragments in registers.
// PV contraction order permuted so the exp'd C-fragment IS the A-fragment:
//   slot t4 <-> key 2*t4, slot t4+4 <-> key 2*t4+1  (A = {c0,c2,c1,c3}).
// V tile stored with row remap sigma(key) = (key>>1) + 32*(key&1) so the
// matching B loads (rows 2t4, 2t4+1) are bank-conflict-free.
// SMEM (floats, stride 72): Kt[64], Vt[64], mk[64].  NO P buffer.
// ---------------------------------------------------------------------------
#define AKT 64
#define ASTR 72
#define AKT_OFF 0
#define AVT_OFF (64 * ASTR)
#define AMK_OFF (AVT_OFF + 64 * ASTR)
#define ATTN_DYN_SMEM ((AMK_OFF + 64) * 4)   // 37120 B

__global__ __launch_bounds__(128, 2) void attn_mma_kernel(const int* __restrict__ mask)
{
    extern __shared__ float sm[];
    float* Kt = sm + AKT_OFF;
    float* Vt = sm + AVT_OFF;
    float* mk = sm + AMK_OFF;
    uint32_t kt_u = smem_u32(Kt), vt_u = smem_u32(Vt);

    int tid = threadIdx.x, w = tid >> 5, lane = tid & 31;
    int g = lane >> 2, t4 = lane & 3;
    int bh = blockIdx.y;
    int b = bh >> 4, h = bh & 15;
    int q0 = blockIdx.x * 128;
    int wrow = w * 32;

    const float* Qb = g_q + (size_t)bh * S_ * D_;
    const float* Kb = g_k + (size_t)bh * S_ * D_;
    const float* Vb = g_v + (size_t)bh * S_ * D_;

    // Prefetch K/V tile 0.  V rows remapped: sigma(r) = (r>>1) + 32*(r&1).
    #pragma unroll
    for (int i = 0; i < 8; i++) {
        int idx = tid + i * 128;
        int row = idx >> 4, c4 = (idx & 15) * 4;
        int vrow = (row >> 1) + 32 * (row & 1);
        cp16(kt_u + (uint32_t)(row * ASTR + c4) * 4,
             Kb + (size_t)row * D_ + c4);
        cp16(vt_u + (uint32_t)(vrow * ASTR + c4) * 4,
             Vb + (size_t)row * D_ + c4);
    }
    CP_COMMIT();
    if (tid < AKT)
        mk[tid] = (mask[b * S_ + tid] == 0) ? -INFINITY : 0.f;

    // Q fragments in registers, both 16-row halves (pre-rounded gmem).
    uint32_t qa0[8][4], qa1[8][4];
    {
        const float* q0p = Qb + (size_t)(q0 + wrow + g) * D_;
        #pragma unroll
        for (int dc = 0; dc < 8; dc++) {
            int d0 = dc * 8 + t4;
            qa0[dc][0] = __float_as_uint(q0p[d0]);
            qa0[dc][1] = __float_as_uint(q0p[8 * D_ + d0]);
            qa0[dc][2] = __float_as_uint(q0p[d0 + 4]);
            qa0[dc][3] = __float_as_uint(q0p[8 * D_ + d0 + 4]);
            qa1[dc][0] = __float_as_uint(q0p[16 * D_ + d0]);
            qa1[dc][1] = __float_as_uint(q0p[24 * D_ + d0]);
            qa1[dc][2] = __float_as_uint(q0p[16 * D_ + d0 + 4]);
            qa1[dc][3] = __float_as_uint(q0p[24 * D_ + d0 + 4]);
        }
    }

    float ov0[8][4], ov1[8][4];
    #pragma unroll
    for (int i = 0; i < 8; i++)
        #pragma unroll
        for (int j = 0; j < 4; j++) { ov0[i][j] = 0.f; ov1[i][j] = 0.f; }
    float l00 = 0.f, l01 = 0.f, l10 = 0.f, l11 = 0.f;

    for (int kt = 0; kt < S_; kt += AKT) {
        CP_WAIT0();
        __syncthreads();

        // QK^T, both 16-row halves, b-fragments shared
        float s0[8][4], s1[8][4];
        #pragma unroll
        for (int i = 0; i < 8; i++)
            #pragma unroll
            for (int j = 0; j < 4; j++) { s0[i][j] = 0.f; s1[i][j] = 0.f; }
        #pragma unroll
        for (int dc = 0; dc < 8; dc++) {
            #pragma unroll
            for (int nf = 0; nf < 8; nf++) {
                const float* bp = Kt + (nf * 8 + g) * ASTR + dc * 8 + t4;
                uint32_t bb[2] = { __float_as_uint(bp[0]),
                                   __float_as_uint(bp[4]) };
                mma_tf32(s0[nf], qa0[dc], bb);
                mma_tf32(s1[nf], qa1[dc], bb);
            }
        }

        // exp (no max; mask via -inf) -> tf32 A-fragments IN REGISTERS.
        // A = {c0, c2, c1, c3}: slot t4 <-> key 2t4, slot t4+4 <-> key 2t4+1.
        uint32_t pa0[8][4], pa1[8][4];
        #pragma unroll
        for (int nf = 0; nf < 8; nf++) {
            float am0 = mk[nf * 8 + 2 * t4], am1 = mk[nf * 8 + 2 * t4 + 1];
            float p00 = __expf(fmaf(s0[nf][0], 0.125f, am0));
            float p01 = __expf(fmaf(s0[nf][1], 0.125f, am1));
            float p02 = __expf(fmaf(s0[nf][2], 0.125f, am0));
            float p03 = __expf(fmaf(s0[nf][3], 0.125f, am1));
            float p10 = __expf(fmaf(s1[nf][0], 0.125f, am0));
            float p11 = __expf(fmaf(s1[nf][1], 0.125f, am1));
            float p12 = __expf(fmaf(s1[nf][2], 0.125f, am0));
            float p13 = __expf(fmaf(s1[nf][3], 0.125f, am1));
            uint32_t u00 = cvt_tf32(p00), u01 = cvt_tf32(p01);
            uint32_t u02 = cvt_tf32(p02), u03 = cvt_tf32(p03);
            uint32_t u10 = cvt_tf32(p10), u11 = cvt_tf32(p11);
            uint32_t u12 = cvt_tf32(p12), u13 = cvt_tf32(p13);
            // accumulate l from the rounded values (consistent with PV)
            l00 += __uint_as_float(u00) + __uint_as_float(u01);
            l01 += __uint_as_float(u02) + __uint_as_float(u03);
            l10 += __uint_as_float(u10) + __uint_as_float(u11);
            l11 += __uint_as_float(u12) + __uint_as_float(u13);
            pa0[nf][0] = u00; pa0[nf][1] = u02; pa0[nf][2] = u01; pa0[nf][3] = u03;
            pa1[nf][0] = u10; pa1[nf][1] = u12; pa1[nf][2] = u11; pa1[nf][3] = u13;
        }

        // PV: A from registers; B = V rows sigma(kc*8+2t4)=kc*4+t4 (+32 for odd)
        #pragma unroll
        for (int kc = 0; kc < 8; kc++) {
            #pragma unroll
            for (int nf = 0; nf < 8; nf++) {
                const float* vp = Vt + (kc * 4 + t4) * ASTR + nf * 8 + g;
                uint32_t bb[2] = { __float_as_uint(vp[0]),
                                   __float_as_uint(vp[32 * ASTR]) };
                mma_tf32(ov0[nf], pa0[kc], bb);
                mma_tf32(ov1[nf], pa1[kc], bb);
            }
        }

        // Stage next tile (after all reads of current Kt/Vt are done).
        if (kt + AKT < S_) {
            __syncthreads();
            #pragma unroll
            for (int i = 0; i < 8; i++) {
                int idx = tid + i * 128;
                int row = idx >> 4, c4 = (idx & 15) * 4;
                int vrow = (row >> 1) + 32 * (row & 1);
                cp16(kt_u + (uint32_t)(row * ASTR + c4) * 4,
                     Kb + (size_t)(kt + AKT + row) * D_ + c4);
                cp16(vt_u + (uint32_t)(vrow * ASTR + c4) * 4,
                     Vb + (size_t)(kt + AKT + row) * D_ + c4);
            }
            CP_COMMIT();
            if (tid < AKT)
                mk[tid] = (mask[b * S_ + kt + AKT + tid] == 0) ? -INFINITY : 0.f;
        }
    }

    // quad-reduce l, normalize, write g_ao [b, s, h*64+d]
    l00 += __shfl_xor_sync(0xffffffffu, l00, 1);
    l00 += __shfl_xor_sync(0xffffffffu, l00, 2);
    l01 += __shfl_xor_sync(0xffffffffu, l01, 1);
    l01 += __shfl_xor_sync(0xffffffffu, l01, 2);
    l10 += __shfl_xor_sync(0xffffffffu, l10, 1);
    l10 += __shfl_xor_sync(0xffffffffu, l10, 2);
    l11 += __shfl_xor_sync(0xffffffffu, l11, 1);
    l11 += __shfl_xor_sync(0xffffffffu, l11, 2);
    float i00 = 1.f / l00, i01 = 1.f / l01, i10 = 1.f / l10, i11 = 1.f / l11;

    int r0 = q0 + wrow + g;
    float* oA = g_ao + ((size_t)(b * S_ + r0))      * E_ + h * D_;
    float* oB = g_ao + ((size_t)(b * S_ + r0 + 8))  * E_ + h * D_;
    float* oC = g_ao + ((size_t)(b * S_ + r0 + 16)) * E_ + h * D_;
    float* oD = g_ao + ((size_t)(b * S_ + r0 + 24)) * E_ + h * D_;
    #pragma unroll
    for (int nf = 0; nf < 8; nf++) {
        int d = nf * 8 + 2 * t4;
        float2 vA = { ov0[nf][0] * i00, ov0[nf][1] * i00 };
        float2 vB = { ov0[nf][2] * i01, ov0[nf][3] * i01 };
        float2 vC = { ov1[nf][0] * i10, ov1[nf][1] * i10 };
        float2 vD = { ov1[nf][2] * i11, ov1[nf][3] * i11 };
        *(float2*)(oA + d) = vA;
        *(float2*)(oB + d) = vB;
        *(float2*)(oC + d) = vC;
        *(float2*)(oD + d) = vD;
    }
}

// ---------------------------------------------------------------------------
extern "C" void kernel_launch(void* const* d_in, const int* in_sizes, int n_in,
                              void* d_out, int out_size)
{
    const float* x    = (const float*)d_in[0];
    const int*   mask = (const int*)  d_in[1];
    const float* Wqkv = (const float*)d_in[2];
    const float* bqkv = (const float*)d_in[3];
    const float* Wout = (const float*)d_in[4];
    const float* bout = (const float*)d_in[5];
    float* out = (float*)d_out;
    (void)in_sizes; (void)n_in; (void)out_size;

    static bool attr_done = false;
    if (!attr_done) {
        cudaFuncSetAttribute(qkv_mma_kernel,
                             cudaFuncAttributeMaxDynamicSharedMemorySize, GEMM_DYN_SMEM);
        cudaFuncSetAttribute(out_mma_kernel,
                             cudaFuncAttributeMaxDynamicSharedMemorySize, GEMM_DYN_SMEM);
        cudaFuncSetAttribute(attn_mma_kernel,
                             cudaFuncAttributeMaxDynamicSharedMemorySize, ATTN_DYN_SMEM);
        attr_done = true;
    }

    transpose_qkv_kernel<<<dim3(N_QKV / 32, E_ / 32), dim3(32, 8)>>>(Wqkv);
    transpose_out_kernel<<<dim3(E_ / 32, E_ / 32), dim3(32, 8)>>>(Wout);

    dim3 g1(N_QKV / 128, M_ROWS / 128);   // 24 x 32
    qkv_mma_kernel<<<g1, 256, GEMM_DYN_SMEM>>>(x, bqkv);

    dim3 g2(S_ / 128, B_ * H_);           // 16 x 32
    attn_mma_kernel<<<g2, 128, ATTN_DYN_SMEM>>>(mask);

    dim3 g3(E_ / 128, M_ROWS / 128);      // 8 x 32
    out_mma_kernel<<<g3, 256, GEMM_DYN_SMEM>>>(bout, out);
}

// round 16
// speedup vs baseline: 1.1188x; 1.0091x over previous
#include <cuda_runtime.h>
#include <math.h>
#include <stdint.h>

// Problem shape (fixed)
#define B_ 2
#define S_ 2048
#define E_ 1024
#define H_ 16
#define D_ 64
#define M_ROWS (B_ * S_)   // 4096
#define N_QKV (3 * E_)     // 3072

// Scratch (__device__ globals per allocation rules). q/k/v tf32-pre-rounded.
__device__ float g_q[B_ * H_ * S_ * D_];   // [b,h,s,d]
__device__ float g_k[B_ * H_ * S_ * D_];
__device__ float g_v[B_ * H_ * S_ * D_];
__device__ float g_ao[B_ * S_ * E_];       // [b,s,e]
__device__ float g_wqkv_t[(size_t)N_QKV * E_];  // Wqkv^T [N][K], tf32-rounded
__device__ float g_wout_t[(size_t)E_ * E_];     // Wout^T [N][K], tf32-rounded

__device__ __forceinline__ uint32_t cvt_tf32(float f) {
    uint32_t u;
    asm("cvt.rn.tf32.f32 %0, %1;" : "=r"(u) : "f"(f));
    return u;
}
__device__ __forceinline__ float rnd_tf32(float f) {
    return __uint_as_float(cvt_tf32(f));
}

__device__ __forceinline__ void mma_tf32(float* c, const uint32_t* a,
                                         const uint32_t* b) {
    asm volatile(
        "mma.sync.aligned.m16n8k8.row.col.f32.tf32.tf32.f32 "
        "{%0,%1,%2,%3}, {%4,%5,%6,%7}, {%8,%9}, {%0,%1,%2,%3};"
        : "+f"(c[0]), "+f"(c[1]), "+f"(c[2]), "+f"(c[3])
        : "r"(a[0]), "r"(a[1]), "r"(a[2]), "r"(a[3]), "r"(b[0]), "r"(b[1]));
}

__device__ __forceinline__ uint32_t smem_u32(const void* p) {
    uint32_t a;
    asm("{ .reg .u64 t; cvta.to.shared.u64 t, %1; cvt.u32.u64 %0, t; }"
        : "=r"(a) : "l"(p));
    return a;
}

__device__ __forceinline__ void cp16(uint32_t dst, const void* src) {
    asm volatile("cp.async.cg.shared.global [%0], [%1], 16;"
                 :: "r"(dst), "l"(src));
}
#define CP_COMMIT() asm volatile("cp.async.commit_group;" ::: "memory")
#define CP_WAIT0()  asm volatile("cp.async.wait_group 0;" ::: "memory")
#define CP_WAIT1()  asm volatile("cp.async.wait_group 1;" ::: "memory")

// ---------------------------------------------------------------------------
// Weight transpose + tf32 rounding:  Wt[n][k] = rn_tf32(W[k][n])
// ---------------------------------------------------------------------------
__device__ __forceinline__ void transpose_body(const float* __restrict__ W,
                                               float* __restrict__ Wt,
                                               int K, int N) {
    __shared__ float tile[32][33];
    int n0 = blockIdx.x * 32, k0 = blockIdx.y * 32;
    int tx = threadIdx.x, ty = threadIdx.y;
    for (int i = ty; i < 32; i += 8)
        tile[i][tx] = W[(size_t)(k0 + i) * N + n0 + tx];
    __syncthreads();
    for (int i = ty; i < 32; i += 8)
        Wt[(size_t)(n0 + i) * K + k0 + tx] = rnd_tf32(tile[tx][i]);
}

__global__ void transpose_qkv_kernel(const float* __restrict__ W) {
    transpose_body(W, g_wqkv_t, E_, N_QKV);
}
__global__ void transpose_out_kernel(const float* __restrict__ W) {
    transpose_body(W, g_wout_t, E_, E_);
}

// ---------------------------------------------------------------------------
// tf32 mma.sync projection GEMM core (R5/R10 structure — measured fastest).
// ---------------------------------------------------------------------------
#define BK 32
#define TSTRIDE 36
#define TILE_WORDS (128 * TSTRIDE)
#define GEMM_DYN_SMEM (2 * 2 * TILE_WORDS * 4)   // 73728 B

struct GemmFrag {
    float acc[4][4][4];   // [mfrag][nfrag][reg]
};

__device__ __forceinline__ void ldg_tile(const float* __restrict__ G,
                                         int rowbase, int kb, int tid,
                                         float4* r) {
    #pragma unroll
    for (int i = 0; i < 4; i++) {
        int idx = tid + i * 256;
        int row = idx >> 3, c4 = idx & 7;
        r[i] = *(const float4*)(G + (size_t)(rowbase + row) * E_ + kb * BK + c4 * 4);
    }
}

__device__ __forceinline__ void sts_tile(float* Sm, int tid, const float4* r) {
    #pragma unroll
    for (int i = 0; i < 4; i++) {
        int idx = tid + i * 256;
        int row = idx >> 3, c4 = idx & 7;
        uint32_t* p = (uint32_t*)(Sm + row * TSTRIDE + c4 * 4);
        p[0] = cvt_tf32(r[i].x);
        p[1] = cvt_tf32(r[i].y);
        p[2] = cvt_tf32(r[i].z);
        p[3] = cvt_tf32(r[i].w);
    }
}

__device__ __forceinline__ void gemm_compute(const float* As, const float* Bs,
                                             int warpM, int warpN, int lane,
                                             GemmFrag& F) {
    int g = lane >> 2, t4 = lane & 3;
    #pragma unroll
    for (int c = 0; c < 4; c++) {
        int k0 = c * 8;
        uint32_t a[4][4], b[4][2];
        #pragma unroll
        for (int mf = 0; mf < 4; mf++) {
            const float* ap = As + (warpM * 64 + mf * 16 + g) * TSTRIDE + k0 + t4;
            a[mf][0] = __float_as_uint(ap[0]);
            a[mf][1] = __float_as_uint(ap[8 * TSTRIDE]);
            a[mf][2] = __float_as_uint(ap[4]);
            a[mf][3] = __float_as_uint(ap[8 * TSTRIDE + 4]);
        }
        #pragma unroll
        for (int nf = 0; nf < 4; nf++) {
            const float* bp = Bs + (warpN * 32 + nf * 8 + g) * TSTRIDE + k0 + t4;
            b[nf][0] = __float_as_uint(bp[0]);
            b[nf][1] = __float_as_uint(bp[4]);
        }
        #pragma unroll
        for (int mf = 0; mf < 4; mf++)
            #pragma unroll
            for (int nf = 0; nf < 4; nf++)
                mma_tf32(F.acc[mf][nf], a[mf], b[nf]);
    }
}

__device__ __forceinline__ void gemm_mainloop(const float* __restrict__ A,
                                              const float* __restrict__ Bt,
                                              int row0, int col0,
                                              float* dynsm, int tid,
                                              int warpM, int warpN, int lane,
                                              GemmFrag& F) {
    float* As[2] = { dynsm,              dynsm + 2 * TILE_WORDS };
    float* Bs[2] = { dynsm + TILE_WORDS, dynsm + 3 * TILE_WORDS };

    float4 ra[4], rb[4];
    ldg_tile(A,  row0, 0, tid, ra);
    ldg_tile(Bt, col0, 0, tid, rb);
    sts_tile(As[0], tid, ra);
    sts_tile(Bs[0], tid, rb);
    __syncthreads();

    const int NBK = E_ / BK;
    for (int kb = 0; kb < NBK; kb++) {
        int cur = kb & 1;
        if (kb + 1 < NBK) {
            ldg_tile(A,  row0, kb + 1, tid, ra);
            ldg_tile(Bt, col0, kb + 1, tid, rb);
        }
        gemm_compute(As[cur], Bs[cur], warpM, warpN, lane, F);
        if (kb + 1 < NBK) {
            sts_tile(As[cur ^ 1], tid, ra);
            sts_tile(Bs[cur ^ 1], tid, rb);
        }
        __syncthreads();
    }
}

// --- QKV GEMM: epilogue scatters tf32-rounded values into g_q/g_k/g_v ---
__global__ __launch_bounds__(256) void qkv_mma_kernel(
    const float* __restrict__ X, const float* __restrict__ bias)
{
    extern __shared__ float dynsm[];
    int tid = threadIdx.x, wid = tid >> 5, lane = tid & 31;
    int warpM = wid & 1, warpN = wid >> 1;
    int row0 = blockIdx.y * 128, col0 = blockIdx.x * 128;

    GemmFrag F;
    #pragma unroll
    for (int i = 0; i < 4; i++)
        #pragma unroll
        for (int j = 0; j < 4; j++)
            #pragma unroll
            for (int k = 0; k < 4; k++) F.acc[i][j][k] = 0.f;

    gemm_mainloop(X, g_wqkv_t, row0, col0, dynsm, tid, warpM, warpN, lane, F);

    int g = lane >> 2, t4 = lane & 3;
    int t = col0 >> 10;
    float* dst = (t == 0) ? g_q : (t == 1) ? g_k : g_v;

    #pragma unroll
    for (int mf = 0; mf < 4; mf++) {
        #pragma unroll
        for (int nf = 0; nf < 4; nf++) {
            int col = col0 + warpN * 32 + nf * 8 + 2 * t4;
            int h = (col & 1023) >> 6;
            int d = col & 63;
            float bx = bias[col], by = bias[col + 1];
            #pragma unroll
            for (int rr = 0; rr < 2; rr++) {
                int row = row0 + warpM * 64 + mf * 16 + g + rr * 8;
                int bb = row >> 11, s = row & (S_ - 1);
                float2 v;
                v.x = rnd_tf32(F.acc[mf][nf][rr * 2 + 0] + bx);  // pre-round
                v.y = rnd_tf32(F.acc[mf][nf][rr * 2 + 1] + by);
                *(float2*)(dst + ((size_t)((bb * H_ + h) * S_ + s)) * D_ + d) = v;
            }
        }
    }
}

// --- Output GEMM: plain epilogue to d_out ---
__global__ __launch_bounds__(256) void out_mma_kernel(
    const float* __restrict__ bias, float* __restrict__ out)
{
    extern __shared__ float dynsm[];
    int tid = threadIdx.x, wid = tid >> 5, lane = tid & 31;
    int warpM = wid & 1, warpN = wid >> 1;
    int row0 = blockIdx.y * 128, col0 = blockIdx.x * 128;

    GemmFrag F;
    #pragma unroll
    for (int i = 0; i < 4; i++)
        #pragma unroll
        for (int j = 0; j < 4; j++)
            #pragma unroll
            for (int k = 0; k < 4; k++) F.acc[i][j][k] = 0.f;

    gemm_mainloop(g_ao, g_wout_t, row0, col0, dynsm, tid, warpM, warpN, lane, F);

    int g = lane >> 2, t4 = lane & 3;
    #pragma unroll
    for (int mf = 0; mf < 4; mf++) {
        #pragma unroll
        for (int nf = 0; nf < 4; nf++) {
            int col = col0 + warpN * 32 + nf * 8 + 2 * t4;
            float bx = bias[col], by = bias[col + 1];
            #pragma unroll
            for (int rr = 0; rr < 2; rr++) {
                int row = row0 + warpM * 64 + mf * 16 + g + rr * 8;
                float2 v;
                v.x = F.acc[mf][nf][rr * 2 + 0] + bx;
                v.y = F.acc[mf][nf][rr * 2 + 1] + by;
                *(float2*)(out + (size_t)row * E_ + col) = v;
            }
        }
    }
}

// ---------------------------------------------------------------------------
// Flash attention, tf32 mma.sync, no-max softmax, REGISTER-RESIDENT P,
// DOUBLE-BUFFERED K/V pipeline (loads for tile i+1 overlap compute of i).
// Grid (S/128, B*H), 128 threads = 4 warps; warp owns 32 q-rows.
// PV contraction order permuted so exp'd C-fragment IS the A-fragment.
// V tile stored with row remap sigma(key) = (key>>1) + 32*(key&1).
// SMEM: 2 x (Kt[64][72] + Vt[64][72]) + mk[2][64].
// ---------------------------------------------------------------------------
#define AKT 64
#define ASTR 72
#define ABUF_WORDS (2 * 64 * ASTR)             // one K+V buffer pair: 9216
#define AMK_OFF (2 * ABUF_WORDS)               // 18432
#define ATTN_DYN_SMEM ((AMK_OFF + 128) * 4)    // 74240 B

__global__ __launch_bounds__(128, 2) void attn_mma_kernel(const int* __restrict__ mask)
{
    extern __shared__ float sm[];
    int tid = threadIdx.x, w = tid >> 5, lane = tid & 31;
    int g = lane >> 2, t4 = lane & 3;
    int bh = blockIdx.y;
    int b = bh >> 4, h = bh & 15;
    int q0 = blockIdx.x * 128;
    int wrow = w * 32;

    const float* Qb = g_q + (size_t)bh * S_ * D_;
    const float* Kb = g_k + (size_t)bh * S_ * D_;
    const float* Vb = g_v + (size_t)bh * S_ * D_;
    uint32_t sm_u = smem_u32(sm);

    // Stage K/V tile at seq offset kt into buffer c (V rows remapped).
    auto stage = [&](int kt, int c) {
        uint32_t kt_u = sm_u + (uint32_t)(c * ABUF_WORDS) * 4;
        uint32_t vt_u = kt_u + (uint32_t)(64 * ASTR) * 4;
        #pragma unroll
        for (int i = 0; i < 8; i++) {
            int idx = tid + i * 128;
            int row = idx >> 4, c4 = (idx & 15) * 4;
            int vrow = (row >> 1) + 32 * (row & 1);
            cp16(kt_u + (uint32_t)(row * ASTR + c4) * 4,
                 Kb + (size_t)(kt + row) * D_ + c4);
            cp16(vt_u + (uint32_t)(vrow * ASTR + c4) * 4,
                 Vb + (size_t)(kt + row) * D_ + c4);
        }
        CP_COMMIT();
        if (tid < AKT)
            sm[AMK_OFF + c * AKT + tid] =
                (mask[b * S_ + kt + tid] == 0) ? -INFINITY : 0.f;
    };

    // Prologue: stage tiles 0 and 1 into buffers 0 and 1.
    stage(0, 0);
    stage(AKT, 1);

    // Q fragments in registers, both 16-row halves (pre-rounded gmem).
    uint32_t qa0[8][4], qa1[8][4];
    {
        const float* q0p = Qb + (size_t)(q0 + wrow + g) * D_;
        #pragma unroll
        for (int dc = 0; dc < 8; dc++) {
            int d0 = dc * 8 + t4;
            qa0[dc][0] = __float_as_uint(q0p[d0]);
            qa0[dc][1] = __float_as_uint(q0p[8 * D_ + d0]);
            qa0[dc][2] = __float_as_uint(q0p[d0 + 4]);
            qa0[dc][3] = __float_as_uint(q0p[8 * D_ + d0 + 4]);
            qa1[dc][0] = __float_as_uint(q0p[16 * D_ + d0]);
            qa1[dc][1] = __float_as_uint(q0p[24 * D_ + d0]);
            qa1[dc][2] = __float_as_uint(q0p[16 * D_ + d0 + 4]);
            qa1[dc][3] = __float_as_uint(q0p[24 * D_ + d0 + 4]);
        }
    }

    float ov0[8][4], ov1[8][4];
    #pragma unroll
    for (int i = 0; i < 8; i++)
        #pragma unroll
        for (int j = 0; j < 4; j++) { ov0[i][j] = 0.f; ov1[i][j] = 0.f; }
    float l00 = 0.f, l01 = 0.f, l10 = 0.f, l11 = 0.f;

    for (int kt = 0; kt < S_; kt += AKT) {
        int cur = (kt >> 6) & 1;
        // Tile kt ready (tile kt+AKT may still be in flight).
        if (kt + AKT < S_) { CP_WAIT1(); } else { CP_WAIT0(); }
        __syncthreads();

        const float* Kt = sm + cur * ABUF_WORDS;
        const float* Vt = Kt + 64 * ASTR;
        const float* mk = sm + AMK_OFF + cur * AKT;

        // QK^T, both 16-row halves, b-fragments shared
        float s0[8][4], s1[8][4];
        #pragma unroll
        for (int i = 0; i < 8; i++)
            #pragma unroll
            for (int j = 0; j < 4; j++) { s0[i][j] = 0.f; s1[i][j] = 0.f; }
        #pragma unroll
        for (int dc = 0; dc < 8; dc++) {
            #pragma unroll
            for (int nf = 0; nf < 8; nf++) {
                const float* bp = Kt + (nf * 8 + g) * ASTR + dc * 8 + t4;
                uint32_t bb[2] = { __float_as_uint(bp[0]),
                                   __float_as_uint(bp[4]) };
                mma_tf32(s0[nf], qa0[dc], bb);
                mma_tf32(s1[nf], qa1[dc], bb);
            }
        }

        // exp (no max; mask via -inf) -> tf32 A-fragments IN REGISTERS.
        uint32_t pa0[8][4], pa1[8][4];
        #pragma unroll
        for (int nf = 0; nf < 8; nf++) {
            float am0 = mk[nf * 8 + 2 * t4], am1 = mk[nf * 8 + 2 * t4 + 1];
            float p00 = __expf(fmaf(s0[nf][0], 0.125f, am0));
            float p01 = __expf(fmaf(s0[nf][1], 0.125f, am1));
            float p02 = __expf(fmaf(s0[nf][2], 0.125f, am0));
            float p03 = __expf(fmaf(s0[nf][3], 0.125f, am1));
            float p10 = __expf(fmaf(s1[nf][0], 0.125f, am0));
            float p11 = __expf(fmaf(s1[nf][1], 0.125f, am1));
            float p12 = __expf(fmaf(s1[nf][2], 0.125f, am0));
            float p13 = __expf(fmaf(s1[nf][3], 0.125f, am1));
            uint32_t u00 = cvt_tf32(p00), u01 = cvt_tf32(p01);
            uint32_t u02 = cvt_tf32(p02), u03 = cvt_tf32(p03);
            uint32_t u10 = cvt_tf32(p10), u11 = cvt_tf32(p11);
            uint32_t u12 = cvt_tf32(p12), u13 = cvt_tf32(p13);
            l00 += __uint_as_float(u00) + __uint_as_float(u01);
            l01 += __uint_as_float(u02) + __uint_as_float(u03);
            l10 += __uint_as_float(u10) + __uint_as_float(u11);
            l11 += __uint_as_float(u12) + __uint_as_float(u13);
            pa0[nf][0] = u00; pa0[nf][1] = u02; pa0[nf][2] = u01; pa0[nf][3] = u03;
            pa1[nf][0] = u10; pa1[nf][1] = u12; pa1[nf][2] = u11; pa1[nf][3] = u13;
        }

        // PV: A from registers; B = V rows (2t4, 2t4+1) via sigma remap.
        #pragma unroll
        for (int kc = 0; kc < 8; kc++) {
            #pragma unroll
            for (int nf = 0; nf < 8; nf++) {
                const float* vp = Vt + (kc * 4 + t4) * ASTR + nf * 8 + g;
                uint32_t bb[2] = { __float_as_uint(vp[0]),
                                   __float_as_uint(vp[32 * ASTR]) };
                mma_tf32(ov0[nf], pa0[kc], bb);
                mma_tf32(ov1[nf], pa1[kc], bb);
            }
        }

        // Restage buffer `cur` with tile kt + 2*AKT.
        if (kt + 2 * AKT < S_) {
            __syncthreads();   // all warps done reading buffer cur
            stage(kt + 2 * AKT, cur);
        }
    }

    // quad-reduce l, normalize, write g_ao [b, s, h*64+d]
    l00 += __shfl_xor_sync(0xffffffffu, l00, 1);
    l00 += __shfl_xor_sync(0xffffffffu, l00, 2);
    l01 += __shfl_xor_sync(0xffffffffu, l01, 1);
    l01 += __shfl_xor_sync(0xffffffffu, l01, 2);
    l10 += __shfl_xor_sync(0xffffffffu, l10, 1);
    l10 += __shfl_xor_sync(0xffffffffu, l10, 2);
    l11 += __shfl_xor_sync(0xffffffffu, l11, 1);
    l11 += __shfl_xor_sync(0xffffffffu, l11, 2);
    float i00 = 1.f / l00, i01 = 1.f / l01, i10 = 1.f / l10, i11 = 1.f / l11;

    int r0 = q0 + wrow + g;
    float* oA = g_ao + ((size_t)(b * S_ + r0))      * E_ + h * D_;
    float* oB = g_ao + ((size_t)(b * S_ + r0 + 8))  * E_ + h * D_;
    float* oC = g_ao + ((size_t)(b * S_ + r0 + 16)) * E_ + h * D_;
    float* oD = g_ao + ((size_t)(b * S_ + r0 + 24)) * E_ + h * D_;
    #pragma unroll
    for (int nf = 0; nf < 8; nf++) {
        int d = nf * 8 + 2 * t4;
        float2 vA = { ov0[nf][0] * i00, ov0[nf][1] * i00 };
        float2 vB = { ov0[nf][2] * i01, ov0[nf][3] * i01 };
        float2 vC = { ov1[nf][0] * i10, ov1[nf][1] * i10 };
        float2 vD = { ov1[nf][2] * i11, ov1[nf][3] * i11 };
        *(float2*)(oA + d) = vA;
        *(float2*)(oB + d) = vB;
        *(float2*)(oC + d) = vC;
        *(float2*)(oD + d) = vD;
    }
}

// ---------------------------------------------------------------------------
extern "C" void kernel_launch(void* const* d_in, const int* in_sizes, int n_in,
                              void* d_out, int out_size)
{
    const float* x    = (const float*)d_in[0];
    const int*   mask = (const int*)  d_in[1];
    const float* Wqkv = (const float*)d_in[2];
    const float* bqkv = (const float*)d_in[3];
    const float* Wout = (const float*)d_in[4];
    const float* bout = (const float*)d_in[5];
    float* out = (float*)d_out;
    (void)in_sizes; (void)n_in; (void)out_size;

    static bool attr_done = false;
    if (!attr_done) {
        cudaFuncSetAttribute(qkv_mma_kernel,
                             cudaFuncAttributeMaxDynamicSharedMemorySize, GEMM_DYN_SMEM);
        cudaFuncSetAttribute(out_mma_kernel,
                             cudaFuncAttributeMaxDynamicSharedMemorySize, GEMM_DYN_SMEM);
        cudaFuncSetAttribute(attn_mma_kernel,
                             cudaFuncAttributeMaxDynamicSharedMemorySize, ATTN_DYN_SMEM);
        attr_done = true;
    }

    transpose_qkv_kernel<<<dim3(N_QKV / 32, E_ / 32), dim3(32, 8)>>>(Wqkv);
    transpose_out_kernel<<<dim3(E_ / 32, E_ / 32), dim3(32, 8)>>>(Wout);

    dim3 g1(N_QKV / 128, M_ROWS / 128);   // 24 x 32
    qkv_mma_kernel<<<g1, 256, GEMM_DYN_SMEM>>>(x, bqkv);

    dim3 g2(S_ / 128, B_ * H_);           // 16 x 32
    attn_mma_kernel<<<g2, 128, ATTN_DYN_SMEM>>>(mask);

    dim3 g3(E_ / 128, M_ROWS / 128);      // 8 x 32
    out_mma_kernel<<<g3, 256, GEMM_DYN_SMEM>>>(bout, out);
}